// round 1
// baseline (speedup 1.0000x reference)
#include <cuda_runtime.h>
#include <cuda_bf16.h>
#include <math.h>

#define NE 2048
#define NP 32768
#define NF 64

// ---------------- scratch (static device, no allocs) ----------------
__device__ float g_R[NP * 16];        // per-pair 4x4 R (row-major p,k,i)
__device__ float g_lvals[NP];         // L1[i,j] gathered per pair
__device__ float g_diag[NE * 16];     // segment-summed R^T R per node
__device__ float g_Dinv[NE * 16];     // Db^{-1/2} per node
__device__ float g_Z[NE * 4 * NF];    // Dinv @ X_t per node-row
__device__ float g_Xcol[NE * NF];     // stalk-mean of X
__device__ float g_hodge[NE * NF];    // hodge term per node
__device__ float g_sheaf[NE * 4 * NF];// Delta_F @ X_t

// ---------------- K1: fused MLP -> R, plus L1 gather ----------------
// warp-per-pair; weights staged in shared (47.5KB static)
__global__ void k_mlp(const float* __restrict__ ef, const float* __restrict__ L1,
                      const float* __restrict__ W1, const float* __restrict__ b1,
                      const float* __restrict__ W2, const float* __restrict__ b2,
                      const float* __restrict__ W3, const float* __restrict__ b3,
                      const int* __restrict__ eidx) {
    __shared__ float W1s[128 * 64];
    __shared__ float W2s[64 * 32];
    __shared__ float W3s[32 * 16];
    __shared__ float b1s[64], b2s[32], b3s[16];
    __shared__ float insh[8][128];
    int tid = threadIdx.x;
    for (int i = tid; i < 128 * 64; i += 256) W1s[i] = W1[i];
    for (int i = tid; i < 64 * 32; i += 256) W2s[i] = W2[i];
    for (int i = tid; i < 32 * 16; i += 256) W3s[i] = W3[i];
    if (tid < 64) b1s[tid] = b1[tid];
    if (tid < 32) b2s[tid] = b2[tid];
    if (tid < 16) b3s[tid] = b3[tid];
    __syncthreads();
    int w = tid >> 5, lane = tid & 31;
    int gw = blockIdx.x * 8 + w;           // 2048 warps total
    for (int p = gw; p < NP; p += 2048) {
        int ii = eidx[2 * p], jj = eidx[2 * p + 1];
        insh[w][lane]      = ef[ii * 64 + lane];
        insh[w][32 + lane] = ef[ii * 64 + 32 + lane];
        insh[w][64 + lane] = ef[jj * 64 + lane];
        insh[w][96 + lane] = ef[jj * 64 + 32 + lane];
        if (lane == 0) g_lvals[p] = L1[(size_t)ii * NE + jj];
        __syncwarp();
        // layer 1: 128 -> 64, each lane owns outputs 2*lane, 2*lane+1
        int o = 2 * lane;
        float a0 = b1s[o], a1 = b1s[o + 1];
        #pragma unroll 8
        for (int k = 0; k < 128; k++) {
            float x = insh[w][k];
            float2 ww = *(const float2*)&W1s[k * 64 + o];
            a0 = fmaf(x, ww.x, a0);
            a1 = fmaf(x, ww.y, a1);
        }
        a0 = fmaxf(a0, 0.f); a1 = fmaxf(a1, 0.f);
        __syncwarp();
        insh[w][o] = a0; insh[w][o + 1] = a1;
        __syncwarp();
        // layer 2: 64 -> 32
        float c = b2s[lane];
        #pragma unroll 8
        for (int k = 0; k < 64; k++) c = fmaf(insh[w][k], W2s[k * 32 + lane], c);
        c = fmaxf(c, 0.f);
        insh[w][64 + lane] = c;
        __syncwarp();
        // layer 3: 32 -> 16 (no relu)
        if (lane < 16) {
            float r = b3s[lane];
            #pragma unroll
            for (int k = 0; k < 32; k++) r = fmaf(insh[w][64 + k], W3s[k * 16 + lane], r);
            g_R[p * 16 + lane] = r;
        }
        __syncwarp();
    }
}

// ---------------- K2: diag = seg-sum(R^T R); Dinv = Db^{-1/2} (Jacobi) ----
__global__ void k_diag_dinv() {
    int w = threadIdx.x >> 5, lane = threadIdx.x & 31;
    int node = blockIdx.x * 4 + w;
    float Fm[16];
    #pragma unroll
    for (int x = 0; x < 16; x++) Fm[x] = 0.f;
    if (lane < 16) {
        int p = node * 16 + lane;
        float Rv[16];
        #pragma unroll
        for (int x = 0; x < 16; x++) Rv[x] = g_R[p * 16 + x];
        #pragma unroll
        for (int a = 0; a < 4; a++)
            #pragma unroll
            for (int b = 0; b < 4; b++) {
                float s = 0.f;
                #pragma unroll
                for (int c = 0; c < 4; c++) s = fmaf(Rv[c * 4 + a], Rv[c * 4 + b], s);
                Fm[a * 4 + b] = s;
            }
    }
    #pragma unroll
    for (int x = 0; x < 16; x++) {
        Fm[x] += __shfl_down_sync(0xffffffffu, Fm[x], 8);
        Fm[x] += __shfl_down_sync(0xffffffffu, Fm[x], 4);
        Fm[x] += __shfl_down_sync(0xffffffffu, Fm[x], 2);
        Fm[x] += __shfl_down_sync(0xffffffffu, Fm[x], 1);
    }
    if (lane == 0) {
        #pragma unroll
        for (int x = 0; x < 16; x++) g_diag[node * 16 + x] = Fm[x];
        const float eps = 1e-4f;
        float A[4][4], V[4][4];
        #pragma unroll
        for (int a = 0; a < 4; a++)
            #pragma unroll
            for (int b = 0; b < 4; b++) {
                A[a][b] = 0.5f * (Fm[a * 4 + b] + Fm[b * 4 + a]);
                V[a][b] = (a == b) ? 1.f : 0.f;
            }
        #pragma unroll
        for (int a = 0; a < 4; a++) A[a][a] += eps;
        const int PI[6] = {0, 0, 0, 1, 1, 2};
        const int QI[6] = {1, 2, 3, 2, 3, 3};
        #pragma unroll
        for (int sweep = 0; sweep < 6; sweep++) {
            #pragma unroll
            for (int r = 0; r < 6; r++) {
                int p = PI[r], q = QI[r];
                float apq = A[p][q];
                if (fabsf(apq) > 1e-20f) {
                    float theta = (A[q][q] - A[p][p]) / (2.f * apq);
                    float t = copysignf(1.f, theta) / (fabsf(theta) + sqrtf(theta * theta + 1.f));
                    float cth = 1.f / sqrtf(t * t + 1.f);
                    float sth = t * cth;
                    float app = A[p][p], aqq = A[q][q];
                    A[p][p] = app - t * apq;
                    A[q][q] = aqq + t * apq;
                    A[p][q] = 0.f; A[q][p] = 0.f;
                    #pragma unroll
                    for (int k = 0; k < 4; k++) {
                        if (k != p && k != q) {
                            float akp = A[k][p], akq = A[k][q];
                            A[k][p] = cth * akp - sth * akq; A[p][k] = A[k][p];
                            A[k][q] = sth * akp + cth * akq; A[q][k] = A[k][q];
                        }
                    }
                    #pragma unroll
                    for (int k = 0; k < 4; k++) {
                        float vkp = V[k][p], vkq = V[k][q];
                        V[k][p] = cth * vkp - sth * vkq;
                        V[k][q] = sth * vkp + cth * vkq;
                    }
                }
            }
        }
        float invs[4];
        #pragma unroll
        for (int k = 0; k < 4; k++) {
            float wv = fmaxf(A[k][k], eps);
            invs[k] = 1.f / sqrtf(wv);
        }
        #pragma unroll
        for (int a = 0; a < 4; a++)
            #pragma unroll
            for (int b = 0; b < 4; b++) {
                float s = 0.f;
                #pragma unroll
                for (int k = 0; k < 4; k++) s = fmaf(V[a][k] * invs[k], V[b][k], s);
                g_Dinv[node * 16 + a * 4 + b] = s;
            }
    }
}

// ---------------- K3: X_t = (Ws1 . Xr) @ Ws2 ; Z = Dinv @ X_t ; Xcol -----
__global__ void k_xt_z(const float* __restrict__ X, const float* __restrict__ Ws1,
                       const float* __restrict__ Ws2) {
    int i = blockIdx.x, f = threadIdx.x;  // 64 threads
    __shared__ float Ysh[4][64];
    float xr[4];
    #pragma unroll
    for (int b = 0; b < 4; b++) xr[b] = X[(4 * i + b) * 64 + f];
    g_Xcol[i * 64 + f] = 0.25f * (xr[0] + xr[1] + xr[2] + xr[3]);
    #pragma unroll
    for (int a = 0; a < 4; a++) {
        float y = 0.f;
        #pragma unroll
        for (int b = 0; b < 4; b++) y = fmaf(Ws1[a * 4 + b], xr[b], y);
        Ysh[a][f] = y;
    }
    __syncthreads();
    float xt[4] = {0.f, 0.f, 0.f, 0.f};
    #pragma unroll 4
    for (int g = 0; g < 64; g++) {
        float w = Ws2[g * 64 + f];
        #pragma unroll
        for (int a = 0; a < 4; a++) xt[a] = fmaf(Ysh[a][g], w, xt[a]);
    }
    float dv[16];
    #pragma unroll
    for (int x = 0; x < 16; x++) dv[x] = g_Dinv[i * 16 + x];
    #pragma unroll
    for (int a = 0; a < 4; a++) {
        float z = 0.f;
        #pragma unroll
        for (int b = 0; b < 4; b++) z = fmaf(dv[a * 4 + b], xt[b], z);
        g_Z[(4 * i + a) * 64 + f] = z;
    }
}

// ---------------- K4: hodge = (L1_norm @ Xcol + Xcol) @ W_hodge ----------
__global__ void k_hodge(const int* __restrict__ eidx, const float* __restrict__ Wh) {
    int i = blockIdx.x, f = threadIdx.x;
    __shared__ float hp[64];
    float s = 0.f;
    #pragma unroll
    for (int p = 0; p < 16; p++) s += fabsf(g_lvals[16 * i + p]);
    float inv = 1.f / (s + 1e-8f);
    float acc = g_Xcol[i * 64 + f];
    #pragma unroll
    for (int p = 0; p < 16; p++) {
        int pp = 16 * i + p;
        int j = eidx[2 * pp + 1];
        acc = fmaf(fabsf(g_lvals[pp]) * inv, g_Xcol[j * 64 + f], acc);
    }
    hp[f] = acc;
    __syncthreads();
    float h = 0.f;
    #pragma unroll 4
    for (int g = 0; g < 64; g++) h = fmaf(hp[g], Wh[g * 64 + f], h);
    g_hodge[i * 64 + f] = h;
}

// ---------------- K5: sheaf = Dinv_i (diag_i Z_i + sum off_p Z_j) --------
__global__ void k_sheaf(const int* __restrict__ eidx, const int* __restrict__ jiidx) {
    int i = blockIdx.x, f = threadIdx.x;
    float acc[4];
    float dg[16];
    #pragma unroll
    for (int x = 0; x < 16; x++) dg[x] = g_diag[i * 16 + x];
    float zi[4];
    #pragma unroll
    for (int b = 0; b < 4; b++) zi[b] = g_Z[(4 * i + b) * 64 + f];
    #pragma unroll
    for (int a = 0; a < 4; a++) {
        float s = 0.f;
        #pragma unroll
        for (int b = 0; b < 4; b++) s = fmaf(dg[a * 4 + b], zi[b], s);
        acc[a] = s;
    }
    for (int k = 0; k < 16; k++) {
        int p = 16 * i + k;
        int j = eidx[2 * p + 1];
        int jp = jiidx[p];
        float l = g_lvals[p];
        float sg = (l > 0.f) ? 1.f : ((l < 0.f) ? -1.f : 0.f);
        float Ra[16], Rb[16];
        #pragma unroll
        for (int x = 0; x < 16; x++) { Ra[x] = g_R[jp * 16 + x]; Rb[x] = g_R[p * 16 + x]; }
        float zj[4];
        #pragma unroll
        for (int b = 0; b < 4; b++) zj[b] = g_Z[(4 * j + b) * 64 + f];
        #pragma unroll
        for (int a = 0; a < 4; a++)
            #pragma unroll
            for (int b = 0; b < 4; b++) {
                float m = 0.f;
                #pragma unroll
                for (int c = 0; c < 4; c++) m = fmaf(Ra[c * 4 + a], Rb[c * 4 + b], m);
                acc[a] = fmaf(-sg * m, zj[b], acc[a]);
            }
    }
    float dv[16];
    #pragma unroll
    for (int x = 0; x < 16; x++) dv[x] = g_Dinv[i * 16 + x];
    #pragma unroll
    for (int a = 0; a < 4; a++) {
        float s = 0.f;
        #pragma unroll
        for (int b = 0; b < 4; b++) s = fmaf(dv[a * 4 + b], acc[b], s);
        g_sheaf[(4 * i + a) * 64 + f] = s;
    }
}

// ---------------- K6: out = X@res_W + res_b - sa*hodge - sb*elu(sheaf) ---
__global__ void k_final(const float* __restrict__ X, const float* __restrict__ resW,
                        const float* __restrict__ resb, const float* __restrict__ alpha,
                        const float* __restrict__ beta, float* __restrict__ out) {
    int g = blockIdx.x, f = threadIdx.x;
    __shared__ float Xsh[4][64];
    #pragma unroll
    for (int b = 0; b < 4; b++) Xsh[b][f] = X[(4 * g + b) * 64 + f];
    __syncthreads();
    float acc[4];
    float bb = resb[f];
    #pragma unroll
    for (int b = 0; b < 4; b++) acc[b] = bb;
    #pragma unroll 4
    for (int k = 0; k < 64; k++) {
        float w = resW[k * 64 + f];
        #pragma unroll
        for (int b = 0; b < 4; b++) acc[b] = fmaf(Xsh[b][k], w, acc[b]);
    }
    float sa = 1.f / (1.f + expf(-alpha[0]));
    float sb = 1.f / (1.f + expf(-beta[0]));
    float hv = g_hodge[g * 64 + f];
    #pragma unroll
    for (int b = 0; b < 4; b++) {
        float s = g_sheaf[(4 * g + b) * 64 + f];
        float e = (s > 0.f) ? s : expm1f(s);
        out[(4 * g + b) * 64 + f] = acc[b] - sa * hv - sb * e;
    }
}

extern "C" void kernel_launch(void* const* d_in, const int* in_sizes, int n_in,
                              void* d_out, int out_size) {
    const float* ef    = (const float*)d_in[0];
    const float* L1    = (const float*)d_in[1];
    const float* X     = (const float*)d_in[2];
    const float* W1    = (const float*)d_in[3];
    const float* b1    = (const float*)d_in[4];
    const float* W2    = (const float*)d_in[5];
    const float* b2    = (const float*)d_in[6];
    const float* W3    = (const float*)d_in[7];
    const float* b3    = (const float*)d_in[8];
    const float* Wh    = (const float*)d_in[9];
    const float* Ws1   = (const float*)d_in[10];
    const float* Ws2   = (const float*)d_in[11];
    const float* resW  = (const float*)d_in[12];
    const float* resb  = (const float*)d_in[13];
    const float* alpha = (const float*)d_in[14];
    const float* beta  = (const float*)d_in[15];
    const int*   eidx  = (const int*)d_in[16];
    const int*   jiidx = (const int*)d_in[17];
    float* out = (float*)d_out;

    k_mlp<<<256, 256>>>(ef, L1, W1, b1, W2, b2, W3, b3, eidx);
    k_diag_dinv<<<512, 128>>>();
    k_xt_z<<<2048, 64>>>(X, Ws1, Ws2);
    k_hodge<<<2048, 64>>>(eidx, Wh);
    k_sheaf<<<2048, 64>>>(eidx, jiidx);
    k_final<<<2048, 64>>>(X, resW, resb, alpha, beta, out);
}

// round 3
// speedup vs baseline: 1.9668x; 1.9668x over previous
#include <cuda_runtime.h>
#include <cuda_bf16.h>
#include <math.h>

#define NE 2048
#define NP 32768

// ---------------- static device scratch ----------------
__device__ float g_U[NE * 64];
__device__ float g_V[NE * 64];
__device__ float g_R[NP * 16];
__device__ float g_off[NP * 16];
__device__ float g_lvals[NP];
__device__ float g_diag[NE * 16];
__device__ float g_Dinv[NE * 16];
__device__ float g_Z[NE * 4 * 64];
__device__ float g_Xcol[NE * 64];

// ---------------- K0: U = ef@W1[:64]+b1 ; V = ef@W1[64:] ----------------
__global__ void k_uv(const float* __restrict__ ef, const float* __restrict__ W1,
                     const float* __restrict__ b1) {
    int nl = threadIdx.x >> 6, f = threadIdx.x & 63;
    int n = blockIdx.x * 4 + nl;
    __shared__ float efs[4][64];
    efs[nl][f] = ef[n * 64 + f];
    __syncthreads();
    float u = b1[f], v = 0.f;
    #pragma unroll 8
    for (int k = 0; k < 64; k++) {
        float x = efs[nl][k];
        u = fmaf(x, W1[k * 64 + f], u);
        v = fmaf(x, W1[(64 + k) * 64 + f], v);
    }
    g_U[n * 64 + f] = u;
    g_V[n * 64 + f] = v;
}

// ---------------- K1: per-pair MLP tail -> R, plus L1 gather ------------
__global__ void k_pair(const float* __restrict__ L1,
                       const float* __restrict__ W2, const float* __restrict__ b2,
                       const float* __restrict__ W3, const float* __restrict__ b3,
                       const int* __restrict__ eidx) {
    __shared__ float W2s[64 * 32];
    __shared__ float W3s[32 * 16];
    __shared__ float b2s[32], b3s[16];
    __shared__ float insh[8][96];
    int tid = threadIdx.x;
    for (int i = tid; i < 64 * 32; i += 256) W2s[i] = W2[i];
    for (int i = tid; i < 32 * 16; i += 256) W3s[i] = W3[i];
    if (tid < 32) b2s[tid] = b2[tid];
    if (tid < 16) b3s[tid] = b3[tid];
    __syncthreads();
    int w = tid >> 5, lane = tid & 31;
    int gw = blockIdx.x * 8 + w;            // 4096 warps, 8 pairs each
    int o = 2 * lane;
    for (int pi = 0; pi < 8; pi++) {
        int p = gw * 8 + pi;
        int ii = eidx[2 * p], jj = eidx[2 * p + 1];
        if (lane == 0) g_lvals[p] = L1[(size_t)ii * NE + jj];
        float2 uu = *(const float2*)&g_U[ii * 64 + o];
        float2 vv = *(const float2*)&g_V[jj * 64 + o];
        insh[w][o]     = fmaxf(uu.x + vv.x, 0.f);
        insh[w][o + 1] = fmaxf(uu.y + vv.y, 0.f);
        __syncwarp();
        // layer 2: 64 -> 32
        float c = b2s[lane];
        #pragma unroll 8
        for (int k = 0; k < 64; k++) c = fmaf(insh[w][k], W2s[k * 32 + lane], c);
        c = fmaxf(c, 0.f);
        insh[w][64 + lane] = c;
        __syncwarp();
        // layer 3: 32 -> 16 (no relu)
        if (lane < 16) {
            float r = b3s[lane];
            #pragma unroll
            for (int k = 0; k < 32; k++) r = fmaf(insh[w][64 + k], W3s[k * 16 + lane], r);
            g_R[p * 16 + lane] = r;
        }
        __syncwarp();
    }
}

// ---------------- K2: diag + Jacobi Dinv + off blocks + Xt/Z/Xcol -------
// block = 256 threads, 8 nodes (=128 pairs) per block, grid 256
__global__ void k_mid(const float* __restrict__ X, const float* __restrict__ Ws1,
                      const float* __restrict__ Ws2, const int* __restrict__ jiidx) {
    __shared__ float sDb[8][16];
    __shared__ float sDinv[8][16];
    __shared__ float Ysh[8][4][64];
    int tid = threadIdx.x;
    int w = tid >> 5, lane = tid & 31;
    int node = blockIdx.x * 8 + w;

    // phase A: diag = segment-sum over the 16 contiguous pairs (warp per node)
    float Fm[16];
    #pragma unroll
    for (int x = 0; x < 16; x++) Fm[x] = 0.f;
    if (lane < 16) {
        int p = node * 16 + lane;
        float Rv[16];
        #pragma unroll
        for (int x = 0; x < 16; x++) Rv[x] = g_R[p * 16 + x];
        #pragma unroll
        for (int a = 0; a < 4; a++)
            #pragma unroll
            for (int b = 0; b < 4; b++) {
                float s = 0.f;
                #pragma unroll
                for (int c = 0; c < 4; c++) s = fmaf(Rv[c * 4 + a], Rv[c * 4 + b], s);
                Fm[a * 4 + b] = s;
            }
    }
    #pragma unroll
    for (int x = 0; x < 16; x++) {
        Fm[x] += __shfl_down_sync(0xffffffffu, Fm[x], 8);
        Fm[x] += __shfl_down_sync(0xffffffffu, Fm[x], 4);
        Fm[x] += __shfl_down_sync(0xffffffffu, Fm[x], 2);
        Fm[x] += __shfl_down_sync(0xffffffffu, Fm[x], 1);
    }
    if (lane == 0) {
        #pragma unroll
        for (int x = 0; x < 16; x++) { sDb[w][x] = Fm[x]; g_diag[node * 16 + x] = Fm[x]; }
    }
    __syncthreads();

    // phase B: threads 0-127 compute off blocks; threads 128-135 run Jacobi
    if (tid < 128) {
        int p = blockIdx.x * 128 + tid;
        int jp = jiidx[p];
        float l = g_lvals[p];
        float msg = (l > 0.f) ? -1.f : ((l < 0.f) ? 1.f : 0.f);  // -sign
        float Ra[16], Rb[16];
        #pragma unroll
        for (int x = 0; x < 16; x++) { Ra[x] = g_R[jp * 16 + x]; Rb[x] = g_R[p * 16 + x]; }
        #pragma unroll
        for (int a = 0; a < 4; a++)
            #pragma unroll
            for (int b = 0; b < 4; b++) {
                float m = 0.f;
                #pragma unroll
                for (int c = 0; c < 4; c++) m = fmaf(Ra[c * 4 + a], Rb[c * 4 + b], m);
                g_off[p * 16 + a * 4 + b] = msg * m;
            }
    } else if (tid < 136) {
        int nl = tid - 128;
        const float eps = 1e-4f;
        float A[4][4], V[4][4];
        #pragma unroll
        for (int a = 0; a < 4; a++)
            #pragma unroll
            for (int b = 0; b < 4; b++) {
                A[a][b] = 0.5f * (sDb[nl][a * 4 + b] + sDb[nl][b * 4 + a]);
                V[a][b] = (a == b) ? 1.f : 0.f;
            }
        #pragma unroll
        for (int a = 0; a < 4; a++) A[a][a] += eps;
        const int PI[6] = {0, 0, 0, 1, 1, 2};
        const int QI[6] = {1, 2, 3, 2, 3, 3};
        #pragma unroll
        for (int sweep = 0; sweep < 6; sweep++) {
            #pragma unroll
            for (int r = 0; r < 6; r++) {
                int p = PI[r], q = QI[r];
                float apq = A[p][q];
                if (fabsf(apq) > 1e-20f) {
                    float theta = (A[q][q] - A[p][p]) / (2.f * apq);
                    float t = copysignf(1.f, theta) / (fabsf(theta) + sqrtf(theta * theta + 1.f));
                    float cth = rsqrtf(t * t + 1.f);
                    float sth = t * cth;
                    float app = A[p][p], aqq = A[q][q];
                    A[p][p] = app - t * apq;
                    A[q][q] = aqq + t * apq;
                    A[p][q] = 0.f; A[q][p] = 0.f;
                    #pragma unroll
                    for (int k = 0; k < 4; k++) {
                        if (k != p && k != q) {
                            float akp = A[k][p], akq = A[k][q];
                            A[k][p] = cth * akp - sth * akq; A[p][k] = A[k][p];
                            A[k][q] = sth * akp + cth * akq; A[q][k] = A[k][q];
                        }
                    }
                    #pragma unroll
                    for (int k = 0; k < 4; k++) {
                        float vkp = V[k][p], vkq = V[k][q];
                        V[k][p] = cth * vkp - sth * vkq;
                        V[k][q] = sth * vkp + cth * vkq;
                    }
                }
            }
        }
        float invs[4];
        #pragma unroll
        for (int k = 0; k < 4; k++) invs[k] = rsqrtf(fmaxf(A[k][k], eps));
        int gnode = blockIdx.x * 8 + nl;
        #pragma unroll
        for (int a = 0; a < 4; a++)
            #pragma unroll
            for (int b = 0; b < 4; b++) {
                float s = 0.f;
                #pragma unroll
                for (int k = 0; k < 4; k++) s = fmaf(V[a][k] * invs[k], V[b][k], s);
                sDinv[nl][a * 4 + b] = s;
                g_Dinv[gnode * 16 + a * 4 + b] = s;
            }
    }
    __syncthreads();

    // phase C: X_t = (Ws1 . Xr) @ Ws2 ; Z = Dinv @ X_t ; Xcol (8 nodes x 64f)
    #pragma unroll
    for (int it = 0; it < 2; it++) {
        int idx = tid + it * 256;
        int nl = idx >> 6, f = idx & 63;
        int n = blockIdx.x * 8 + nl;
        float xr[4];
        #pragma unroll
        for (int b = 0; b < 4; b++) xr[b] = X[(4 * n + b) * 64 + f];
        g_Xcol[n * 64 + f] = 0.25f * (xr[0] + xr[1] + xr[2] + xr[3]);
        #pragma unroll
        for (int a = 0; a < 4; a++) {
            float y = 0.f;
            #pragma unroll
            for (int b = 0; b < 4; b++) y = fmaf(Ws1[a * 4 + b], xr[b], y);
            Ysh[nl][a][f] = y;
        }
    }
    __syncthreads();
    #pragma unroll
    for (int it = 0; it < 2; it++) {
        int idx = tid + it * 256;
        int nl = idx >> 6, f = idx & 63;
        int n = blockIdx.x * 8 + nl;
        float xt[4] = {0.f, 0.f, 0.f, 0.f};
        #pragma unroll 4
        for (int g = 0; g < 64; g++) {
            float w2 = Ws2[g * 64 + f];
            #pragma unroll
            for (int a = 0; a < 4; a++) xt[a] = fmaf(Ysh[nl][a][g], w2, xt[a]);
        }
        float dv[16];
        #pragma unroll
        for (int x = 0; x < 16; x++) dv[x] = sDinv[nl][x];
        #pragma unroll
        for (int a = 0; a < 4; a++) {
            float z = 0.f;
            #pragma unroll
            for (int b = 0; b < 4; b++) z = fmaf(dv[a * 4 + b], xt[b], z);
            g_Z[(4 * n + a) * 64 + f] = z;
        }
    }
}

// ---------------- K3: hodge + sheaf + residual + output -----------------
// block = 256 threads, 4 nodes per block, grid 512
__global__ void k_out(const int* __restrict__ eidx, const float* __restrict__ Wh,
                      const float* __restrict__ X, const float* __restrict__ resW,
                      const float* __restrict__ resb, const float* __restrict__ alpha,
                      const float* __restrict__ beta, float* __restrict__ out) {
    int tid = threadIdx.x;
    int nl = tid >> 6, f = tid & 63;
    int i = blockIdx.x * 4 + nl;
    __shared__ float hp[4][64];
    __shared__ float Xsh[4][4][64];
    __shared__ float offs[4][256];

    // stage X rows, off blocks
    float xv[4];
    #pragma unroll
    for (int b = 0; b < 4; b++) { xv[b] = X[(4 * i + b) * 64 + f]; Xsh[nl][b][f] = xv[b]; }
    ((float4*)offs[nl])[f] = ((const float4*)&g_off[(size_t)i * 256])[f];

    // hodge row part
    float s = 0.f;
    #pragma unroll
    for (int p = 0; p < 16; p++) s += fabsf(g_lvals[16 * i + p]);
    float inv = 1.f / (s + 1e-8f);
    float acc = g_Xcol[i * 64 + f];
    #pragma unroll
    for (int p = 0; p < 16; p++) {
        int pp = 16 * i + p;
        int j = eidx[2 * pp + 1];
        acc = fmaf(fabsf(g_lvals[pp]) * inv, g_Xcol[j * 64 + f], acc);
    }
    hp[nl][f] = acc;

    // sheaf accumulation: diag_i Z_i (+ staged off blocks after sync)
    float dg[16];
    #pragma unroll
    for (int x = 0; x < 16; x++) dg[x] = g_diag[i * 16 + x];
    float zi[4];
    #pragma unroll
    for (int b = 0; b < 4; b++) zi[b] = g_Z[(4 * i + b) * 64 + f];
    float accs[4];
    #pragma unroll
    for (int a = 0; a < 4; a++) {
        float t = 0.f;
        #pragma unroll
        for (int b = 0; b < 4; b++) t = fmaf(dg[a * 4 + b], zi[b], t);
        accs[a] = t;
    }
    __syncthreads();

    for (int k = 0; k < 16; k++) {
        int p = 16 * i + k;
        int j = eidx[2 * p + 1];
        float zj[4];
        #pragma unroll
        for (int b = 0; b < 4; b++) zj[b] = g_Z[(4 * j + b) * 64 + f];
        #pragma unroll
        for (int a = 0; a < 4; a++)
            #pragma unroll
            for (int b = 0; b < 4; b++)
                accs[a] = fmaf(offs[nl][k * 16 + a * 4 + b], zj[b], accs[a]);
    }
    float dv[16];
    #pragma unroll
    for (int x = 0; x < 16; x++) dv[x] = g_Dinv[i * 16 + x];
    float sh[4];
    #pragma unroll
    for (int a = 0; a < 4; a++) {
        float t = 0.f;
        #pragma unroll
        for (int b = 0; b < 4; b++) t = fmaf(dv[a * 4 + b], accs[b], t);
        sh[a] = t;
    }

    // hodge matmul
    float h = 0.f;
    #pragma unroll 4
    for (int g = 0; g < 64; g++) h = fmaf(hp[nl][g], Wh[g * 64 + f], h);

    // residual matmul
    float r[4];
    float bb = resb[f];
    #pragma unroll
    for (int b = 0; b < 4; b++) r[b] = bb;
    #pragma unroll 4
    for (int k = 0; k < 64; k++) {
        float w = resW[k * 64 + f];
        #pragma unroll
        for (int b = 0; b < 4; b++) r[b] = fmaf(Xsh[nl][b][k], w, r[b]);
    }

    float sa = 1.f / (1.f + expf(-alpha[0]));
    float sb = 1.f / (1.f + expf(-beta[0]));
    #pragma unroll
    for (int b = 0; b < 4; b++) {
        float e = (sh[b] > 0.f) ? sh[b] : expm1f(sh[b]);
        out[(4 * i + b) * 64 + f] = r[b] - sa * h - sb * e;
    }
}

extern "C" void kernel_launch(void* const* d_in, const int* in_sizes, int n_in,
                              void* d_out, int out_size) {
    const float* ef    = (const float*)d_in[0];
    const float* L1    = (const float*)d_in[1];
    const float* X     = (const float*)d_in[2];
    const float* W1    = (const float*)d_in[3];
    const float* b1    = (const float*)d_in[4];
    const float* W2    = (const float*)d_in[5];
    const float* b2    = (const float*)d_in[6];
    const float* W3    = (const float*)d_in[7];
    const float* b3    = (const float*)d_in[8];
    const float* Wh    = (const float*)d_in[9];
    const float* Ws1   = (const float*)d_in[10];
    const float* Ws2   = (const float*)d_in[11];
    const float* resW  = (const float*)d_in[12];
    const float* resb  = (const float*)d_in[13];
    const float* alpha = (const float*)d_in[14];
    const float* beta  = (const float*)d_in[15];
    const int*   eidx  = (const int*)d_in[16];
    const int*   jiidx = (const int*)d_in[17];
    float* out = (float*)d_out;

    k_uv<<<512, 256>>>(ef, W1, b1);
    k_pair<<<512, 256>>>(L1, W2, b2, W3, b3, eidx);
    k_mid<<<256, 256>>>(X, Ws1, Ws2, jiidx);
    k_out<<<512, 256>>>(eidx, Wh, X, resW, resb, alpha, beta, out);
}